// round 11
// baseline (speedup 1.0000x reference)
#include <cuda_runtime.h>
#include <math.h>

#define B_ROWS 128
#define V_COLS 128256
#define V4 (V_COLS / 4)              // 32064 float4 per row
#define TOTAL_Q4 (B_ROWS * V4)       // 4104192 float4 total
#define NCTA 888                     // 148 SMs * 6 CTAs -> perfectly balanced
#define CHUNK ((TOTAL_Q4 + NCTA - 1) / NCTA)   // 4622 (< V4 -> spans <= 2 rows)
#define THREADS 256

// Per-row best keys (packed). Zero-init at load; last CTA resets each replay.
__device__ unsigned long long d_best_s[B_ROWS];
__device__ unsigned long long d_best_g[B_ROWS];
__device__ int d_done;   // completion counter, self-resetting

// Pack (value, index) so 64-bit unsigned max == (max value, then MIN index)
__device__ __forceinline__ unsigned long long pack_key(float v, int idx) {
    unsigned int b = __float_as_uint(v);
    b = (b & 0x80000000u) ? ~b : (b | 0x80000000u);   // order-preserving map
    return ((unsigned long long)b << 32) | (unsigned int)(~idx);
}

__device__ __forceinline__ unsigned long long kmax64(unsigned long long a,
                                                     unsigned long long b) {
    return a > b ? a : b;
}

// w = -log(uc), RELATIVE-accurate on [1e-10, 1-1e-7] (proven R5 form):
//  - u <= 0.96: MUFU lg2 (w >= 0.0408 -> rel err <= ~8e-6)
//  - u  > 0.96: 4-term log1p poly on f = u-1 (rel err <= 5e-7)
__device__ __forceinline__ float neg_log_acc(float uc) {
    float w_m = -__logf(uc);
    float f = uc - 1.0f;
    float p = -0.25f;
    p = fmaf(p, f, 0.333333333f);
    p = fmaf(p, f, -0.5f);
    float w_p = -fmaf(f * f, p, f);             // -log1p(f)
    return (uc > 0.96f) ? w_p : w_m;
}

__device__ __forceinline__ float score1(float x, float uv, float inv) {
    const float U_LO = 1e-10f;
    const float U_HI = __uint_as_float(0x3F7FFFFEu);   // float(1 - 1e-7)
    float uc = fminf(fmaxf(uv, U_LO), U_HI);
    float w  = neg_log_acc(uc);
    float g  = -__logf(w);
    return fmaf(x, inv, g);
}

// 4 independent scores, tree-reduced (strict > keeps lower index), one update.
__device__ __forceinline__ void body4(float4 l4, float4 u4, int base, float inv,
                                      float& bs, int& bsi) {
    float v0 = score1(l4.x, u4.x, inv);
    float v1 = score1(l4.y, u4.y, inv);
    float v2 = score1(l4.z, u4.z, inv);
    float v3 = score1(l4.w, u4.w, inv);

    float m01 = v0; int i01 = 0;
    if (v1 > m01) { m01 = v1; i01 = 1; }
    float m23 = v2; int i23 = 2;
    if (v3 > m23) { m23 = v3; i23 = 3; }
    float m = m01;  int im = i01;
    if (m23 > m)  { m = m23;  im = i23; }

    if (m > bs) { bs = m; bsi = base + im; }
}

__global__ __launch_bounds__(THREADS, 6)
void sampler_fused_kernel(const float* __restrict__ logits,
                          const float* __restrict__ temps,
                          const float* __restrict__ u,
                          float* __restrict__ out) {
    const int q_start = blockIdx.x * CHUNK;
    const int q_end   = min(q_start + CHUNK, TOTAL_Q4);

    const float4* __restrict__ lg = reinterpret_cast<const float4*>(logits);
    const float4* __restrict__ uu = reinterpret_cast<const float4*>(u);

    __shared__ unsigned long long sg[THREADS / 32];
    __shared__ unsigned long long ss[THREADS / 32];
    __shared__ int last_flag;
    if (threadIdx.x == 0) last_flag = 0;

    const int row0 = q_start / V4;
    const int row1 = (q_end - 1) / V4;     // row0 or row0+1 (CHUNK < V4)

    for (int r = row0; r <= row1; r++) {
        __syncthreads();                   // smem reuse across row-parts
        const int a = max(q_start, r * V4);
        const int b = min(q_end, (r + 1) * V4);
        const int rbase = r * V4;

        const float t_raw = temps[r];
        const float inv   = 1.0f / fmaxf(t_raw, 1e-6f);
        const bool  need_greedy = (t_raw <= 1e-6f);

        float bg = __int_as_float(0xFF800000);  int bgi = 0;
        float bs = __int_as_float(0xFF800000);  int bsi = 0;

        int q = a + threadIdx.x;
        if (q < b) {
            if (need_greedy) {
                for (; q < b; q += THREADS) {
                    float4 l4 = __ldcs(lg + q);
                    float4 u4 = __ldcs(uu + q);
                    const int base = (q - rbase) << 2;
                    float lv[4] = {l4.x, l4.y, l4.z, l4.w};
                    #pragma unroll
                    for (int j = 0; j < 4; j++)
                        if (lv[j] > bg) { bg = lv[j]; bgi = base + j; }
                    body4(l4, u4, base, inv, bs, bsi);
                }
            } else {
                // Software pipeline: next loads issue before this body.
                float4 lc = __ldcs(lg + q);
                float4 uc = __ldcs(uu + q);
                for (int qn = q + THREADS; qn < b; qn += THREADS) {
                    float4 ln = __ldcs(lg + qn);
                    float4 un = __ldcs(uu + qn);
                    body4(lc, uc, (q - rbase) << 2, inv, bs, bsi);
                    lc = ln; uc = un; q = qn;
                }
                body4(lc, uc, (q - rbase) << 2, inv, bs, bsi);
            }
        }

        // Block reduction on packed keys
        unsigned long long kg = pack_key(bg, bgi);
        unsigned long long ks = pack_key(bs, bsi);

        #pragma unroll
        for (int o = 16; o > 0; o >>= 1) {
            kg = kmax64(kg, __shfl_xor_sync(0xffffffffu, kg, o));
            ks = kmax64(ks, __shfl_xor_sync(0xffffffffu, ks, o));
        }
        const int wid  = threadIdx.x >> 5;
        const int lane = threadIdx.x & 31;
        if (lane == 0) { sg[wid] = kg; ss[wid] = ks; }
        __syncthreads();

        if (threadIdx.x == 0) {
            #pragma unroll
            for (int i = 1; i < THREADS / 32; i++) {
                kg = kmax64(kg, sg[i]);
                ks = kmax64(ks, ss[i]);
            }
            atomicMax(&d_best_s[r], ks);
            if (need_greedy) atomicMax(&d_best_g[r], kg);
        }
    }

    // Completion: last CTA finalizes all rows (and resets state for replay).
    if (threadIdx.x == 0) {
        __threadfence();                       // publish atomics
        int old = atomicAdd(&d_done, 1);
        if (old == NCTA - 1) {
            d_done = 0;                        // self-reset
            last_flag = 1;
        }
    }
    __syncthreads();

    if (last_flag) {
        __threadfence();
        const int r = threadIdx.x;
        if (r < B_ROWS) {
            unsigned long long ms = d_best_s[r];
            unsigned long long mg = d_best_g[r];
            float tr = temps[r];
            int idx = (tr <= 1e-6f) ? (int)~(unsigned int)mg
                                    : (int)~(unsigned int)ms;
            out[r] = (float)idx;               // output dtype is float32
            d_best_s[r] = 0ull;                // reset for next replay
            d_best_g[r] = 0ull;
        }
    }
}

extern "C" void kernel_launch(void* const* d_in, const int* in_sizes, int n_in,
                              void* d_out, int out_size) {
    const float* logits = (const float*)d_in[0];
    const float* temps  = (const float*)d_in[1];
    const float* u      = (const float*)d_in[2];
    float* out = (float*)d_out;

    sampler_fused_kernel<<<NCTA, THREADS>>>(logits, temps, u, out);
}

// round 12
// speedup vs baseline: 1.0088x; 1.0088x over previous
#include <cuda_runtime.h>
#include <math.h>

#define B_ROWS 128
#define V_COLS 128256
#define V4 (V_COLS / 4)          // 32064 float4 per row
#define SPLIT 6                  // 768 CTAs (proven best geometry)
#define SEG_Q (V4 / SPLIT)       // 5344 float4 per segment (exact)
#define THREADS 256
#define TILE_Q4 512              // 512 float4 = 8KB per array per tile
#define NTILES ((SEG_Q + TILE_Q4 - 1) / TILE_Q4)   // 11 (last tile = 224)

// Per-(row,segment) partials; counter self-resets -> graph-replay safe.
__device__ unsigned long long d_part_g[B_ROWS * SPLIT];
__device__ unsigned long long d_part_s[B_ROWS * SPLIT];
__device__ int d_count[B_ROWS];

// ---------------- mbarrier / bulk-async helpers ----------------
__device__ __forceinline__ unsigned smem_u32(const void* p) {
    return (unsigned)__cvta_generic_to_shared(p);
}
__device__ __forceinline__ void mbar_init(unsigned a, unsigned cnt) {
    asm volatile("mbarrier.init.shared.b64 [%0], %1;" :: "r"(a), "r"(cnt) : "memory");
}
__device__ __forceinline__ void mbar_expect_tx(unsigned a, unsigned bytes) {
    asm volatile("mbarrier.arrive.expect_tx.shared.b64 _, [%0], %1;"
                 :: "r"(a), "r"(bytes) : "memory");
}
__device__ __forceinline__ void bulk_g2s(unsigned dst, const void* src,
                                         unsigned bytes, unsigned mbar) {
    asm volatile("cp.async.bulk.shared::cta.global.mbarrier::complete_tx::bytes "
                 "[%0], [%1], %2, [%3];"
                 :: "r"(dst), "l"(src), "r"(bytes), "r"(mbar) : "memory");
}
__device__ __forceinline__ void mbar_wait(unsigned a, unsigned parity) {
    asm volatile(
        "{\n\t"
        ".reg .pred P1;\n\t"
        "WAIT_LOOP_%=:\n\t"
        "mbarrier.try_wait.parity.acquire.cta.shared::cta.b64 P1, [%0], %1, 0x989680;\n\t"
        "@P1 bra.uni WAIT_DONE_%=;\n\t"
        "bra.uni WAIT_LOOP_%=;\n\t"
        "WAIT_DONE_%=:\n\t"
        "}"
        :: "r"(a), "r"(parity) : "memory");
}

// ---------------- proven math (byte-identical to R5/R10) ----------------
__device__ __forceinline__ unsigned long long pack_key(float v, int idx) {
    unsigned int b = __float_as_uint(v);
    b = (b & 0x80000000u) ? ~b : (b | 0x80000000u);
    return ((unsigned long long)b << 32) | (unsigned int)(~idx);
}
__device__ __forceinline__ unsigned long long kmax64(unsigned long long a,
                                                     unsigned long long b) {
    return a > b ? a : b;
}
__device__ __forceinline__ float neg_log_acc(float uc) {
    float w_m = -__logf(uc);
    float f = uc - 1.0f;
    float p = -0.25f;
    p = fmaf(p, f, 0.333333333f);
    p = fmaf(p, f, -0.5f);
    float w_p = -fmaf(f * f, p, f);
    return (uc > 0.96f) ? w_p : w_m;
}
__device__ __forceinline__ float score1(float x, float uv, float inv) {
    const float U_LO = 1e-10f;
    const float U_HI = __uint_as_float(0x3F7FFFFEu);
    float uc = fminf(fmaxf(uv, U_LO), U_HI);
    float w  = neg_log_acc(uc);
    float g  = -__logf(w);
    return fmaf(x, inv, g);
}
__device__ __forceinline__ void body4(float4 l4, float4 u4, int base, float inv,
                                      float& bs, int& bsi) {
    float v0 = score1(l4.x, u4.x, inv);
    float v1 = score1(l4.y, u4.y, inv);
    float v2 = score1(l4.z, u4.z, inv);
    float v3 = score1(l4.w, u4.w, inv);
    float m01 = v0; int i01 = 0;
    if (v1 > m01) { m01 = v1; i01 = 1; }
    float m23 = v2; int i23 = 2;
    if (v3 > m23) { m23 = v3; i23 = 3; }
    float m = m01;  int im = i01;
    if (m23 > m)  { m = m23;  im = i23; }
    if (m > bs) { bs = m; bsi = base + im; }
}

__global__ __launch_bounds__(THREADS, 6)
void sampler_fused_kernel(const float* __restrict__ logits,
                          const float* __restrict__ temps,
                          const float* __restrict__ u,
                          float* __restrict__ out) {
    __shared__ float4 s_l[2][TILE_Q4];
    __shared__ float4 s_u[2][TILE_Q4];
    __shared__ unsigned long long s_mbar[2];
    __shared__ unsigned long long sg[THREADS / 32];
    __shared__ unsigned long long ss[THREADS / 32];

    const int seg = blockIdx.x;
    const int row = blockIdx.y;
    const int tid = threadIdx.x;

    const float4* __restrict__ lg = reinterpret_cast<const float4*>(logits) + (size_t)row * V4;
    const float4* __restrict__ uu = reinterpret_cast<const float4*>(u)      + (size_t)row * V4;

    const float t_raw = temps[row];
    const float inv   = 1.0f / fmaxf(t_raw, 1e-6f);
    const bool  need_greedy = (t_raw <= 1e-6f);

    const int q0 = seg * SEG_Q;             // row-relative float4 offset

    const unsigned mb0 = smem_u32(&s_mbar[0]);
    if (tid == 0) {
        mbar_init(mb0, 1);
        mbar_init(mb0 + 8, 1);
        asm volatile("fence.proxy.async.shared::cta;" ::: "memory");
    }
    __syncthreads();

    float bg = __int_as_float(0xFF800000);  int bgi = 0;
    float bs = __int_as_float(0xFF800000);  int bsi = 0;

    // issue tile t's bulk copies (tid 0 only)
    auto issue = [&](int t) {
        const int start = q0 + t * TILE_Q4;
        const int cnt   = min(TILE_Q4, q0 + SEG_Q - start);
        const unsigned bytes = (unsigned)cnt * 16u;
        const int st = t & 1;
        const unsigned mb = mb0 + 8u * st;
        mbar_expect_tx(mb, 2u * bytes);
        bulk_g2s(smem_u32(&s_l[st][0]), lg + start, bytes, mb);
        bulk_g2s(smem_u32(&s_u[st][0]), uu + start, bytes, mb);
    };

    if (tid == 0) issue(0);

    for (int t = 0; t < NTILES; t++) {
        if (tid == 0 && t + 1 < NTILES) issue(t + 1);

        const int st = t & 1;
        mbar_wait(mb0 + 8u * st, (t >> 1) & 1);

        const int start = q0 + t * TILE_Q4;
        const int cnt   = min(TILE_Q4, q0 + SEG_Q - start);

        if (need_greedy) {
            for (int i = tid; i < cnt; i += THREADS) {
                float4 l4 = s_l[st][i];
                float4 u4 = s_u[st][i];
                const int base = (start + i) << 2;
                float lv[4] = {l4.x, l4.y, l4.z, l4.w};
                #pragma unroll
                for (int j = 0; j < 4; j++)
                    if (lv[j] > bg) { bg = lv[j]; bgi = base + j; }
                body4(l4, u4, base, inv, bs, bsi);
            }
        } else {
            for (int i = tid; i < cnt; i += THREADS) {
                float4 l4 = s_l[st][i];
                float4 u4 = s_u[st][i];
                body4(l4, u4, (start + i) << 2, inv, bs, bsi);
            }
        }
        __syncthreads();   // stage st fully consumed before reissue at t+2
    }

    // Block reduction on packed keys
    unsigned long long kg = pack_key(bg, bgi);
    unsigned long long ks = pack_key(bs, bsi);
    #pragma unroll
    for (int o = 16; o > 0; o >>= 1) {
        kg = kmax64(kg, __shfl_xor_sync(0xffffffffu, kg, o));
        ks = kmax64(ks, __shfl_xor_sync(0xffffffffu, ks, o));
    }
    const int wid  = tid >> 5;
    const int lane = tid & 31;
    if (lane == 0) { sg[wid] = kg; ss[wid] = ks; }
    __syncthreads();

    if (tid == 0) {
        #pragma unroll
        for (int i = 1; i < THREADS / 32; i++) {
            kg = kmax64(kg, sg[i]);
            ks = kmax64(ks, ss[i]);
        }
        d_part_g[row * SPLIT + seg] = kg;
        d_part_s[row * SPLIT + seg] = ks;

        __threadfence();
        int old = atomicAdd(&d_count[row], 1);
        if (old == SPLIT - 1) {
            d_count[row] = 0;
            __threadfence();
            unsigned long long mg = 0ull, ms = 0ull;
            #pragma unroll
            for (int i = 0; i < SPLIT; i++) {
                mg = kmax64(mg, d_part_g[row * SPLIT + i]);
                ms = kmax64(ms, d_part_s[row * SPLIT + i]);
            }
            int ig = (int)~(unsigned int)mg;
            int is = (int)~(unsigned int)ms;
            out[row] = (float)(need_greedy ? ig : is);
        }
    }
}

extern "C" void kernel_launch(void* const* d_in, const int* in_sizes, int n_in,
                              void* d_out, int out_size) {
    const float* logits = (const float*)d_in[0];
    const float* temps  = (const float*)d_in[1];
    const float* u      = (const float*)d_in[2];
    float* out = (float*)d_out;

    dim3 grid(SPLIT, B_ROWS);
    sampler_fused_kernel<<<grid, THREADS>>>(logits, temps, u, out);
}

// round 13
// speedup vs baseline: 1.0748x; 1.0654x over previous
#include <cuda_runtime.h>
#include <math.h>

#define B_ROWS 128
#define V_COLS 128256
#define V4 (V_COLS / 4)          // 32064 float4 per row
#define SPLIT 6                  // 768 CTAs -> proven best geometry
#define SEG_Q (V4 / SPLIT)       // 5344 float4 per segment (exact)
#define THREADS 256

// Per-(row,segment) partials; counter self-resets -> graph-replay safe.
__device__ unsigned long long d_part_g[B_ROWS * SPLIT];
__device__ unsigned long long d_part_s[B_ROWS * SPLIT];
__device__ int d_count[B_ROWS];

// Streaming load with 256B L2 fetch granularity: sequential streams ->
// fewer L2 requests, longer HBM bursts.
__device__ __forceinline__ float4 ldg_stream256(const float4* p) {
    float4 v;
    asm("ld.global.nc.L2::256B.v4.f32 {%0,%1,%2,%3}, [%4];"
        : "=f"(v.x), "=f"(v.y), "=f"(v.z), "=f"(v.w) : "l"(p));
    return v;
}

// Pack (value, index) so 64-bit unsigned max == (max value, then MIN index)
__device__ __forceinline__ unsigned long long pack_key(float v, int idx) {
    unsigned int b = __float_as_uint(v);
    b = (b & 0x80000000u) ? ~b : (b | 0x80000000u);   // order-preserving map
    return ((unsigned long long)b << 32) | (unsigned int)(~idx);
}

__device__ __forceinline__ unsigned long long kmax64(unsigned long long a,
                                                     unsigned long long b) {
    return a > b ? a : b;
}

// w = -log(uc), RELATIVE-accurate on [1e-10, 1-1e-7] (proven R5 form):
//  - u <= 0.96: MUFU lg2 (w >= 0.0408 -> rel err <= ~8e-6)
//  - u  > 0.96: 4-term log1p poly on f = u-1 (rel err <= 5e-7)
__device__ __forceinline__ float neg_log_acc(float uc) {
    float w_m = -__logf(uc);
    float f = uc - 1.0f;
    float p = -0.25f;
    p = fmaf(p, f, 0.333333333f);
    p = fmaf(p, f, -0.5f);
    float w_p = -fmaf(f * f, p, f);             // -log1p(f)
    return (uc > 0.96f) ? w_p : w_m;
}

__device__ __forceinline__ float score1(float x, float uv, float inv) {
    const float U_LO = 1e-10f;
    const float U_HI = __uint_as_float(0x3F7FFFFEu);   // float(1 - 1e-7)
    float uc = fminf(fmaxf(uv, U_LO), U_HI);
    float w  = neg_log_acc(uc);
    float g  = -__logf(w);
    return fmaf(x, inv, g);
}

// 4 independent scores, tree-reduced (strict > keeps lower index), one update.
__device__ __forceinline__ void body4(float4 l4, float4 u4, int base, float inv,
                                      float& bs, int& bsi) {
    float v0 = score1(l4.x, u4.x, inv);
    float v1 = score1(l4.y, u4.y, inv);
    float v2 = score1(l4.z, u4.z, inv);
    float v3 = score1(l4.w, u4.w, inv);

    float m01 = v0; int i01 = 0;
    if (v1 > m01) { m01 = v1; i01 = 1; }
    float m23 = v2; int i23 = 2;
    if (v3 > m23) { m23 = v3; i23 = 3; }
    float m = m01;  int im = i01;
    if (m23 > m)  { m = m23;  im = i23; }

    if (m > bs) { bs = m; bsi = base + im; }
}

__global__ __launch_bounds__(THREADS, 6)
void sampler_fused_kernel(const float* __restrict__ logits,
                          const float* __restrict__ temps,
                          const float* __restrict__ u,
                          float* __restrict__ out) {
    const int seg = blockIdx.x;
    const int row = blockIdx.y;

    const float4* __restrict__ lg = reinterpret_cast<const float4*>(logits) + (size_t)row * V4;
    const float4* __restrict__ uu = reinterpret_cast<const float4*>(u)      + (size_t)row * V4;

    const float t_raw = temps[row];
    const float inv   = 1.0f / fmaxf(t_raw, 1e-6f);
    const bool  need_greedy = (t_raw <= 1e-6f);

    const int q0 = seg * SEG_Q;
    const int q1 = q0 + SEG_Q;

    float bg = __int_as_float(0xFF800000);  int bgi = 0;
    float bs = __int_as_float(0xFF800000);  int bsi = 0;

    if (need_greedy) {
        // Rare path (temps ~ U[0,1)): also track raw-logits argmax
        for (int q = q0 + threadIdx.x; q < q1; q += THREADS) {
            float4 l4 = ldg_stream256(lg + q);
            float4 u4 = ldg_stream256(uu + q);
            const int base = q << 2;
            float lv[4] = {l4.x, l4.y, l4.z, l4.w};
            #pragma unroll
            for (int j = 0; j < 4; j++)
                if (lv[j] > bg) { bg = lv[j]; bgi = base + j; }
            body4(l4, u4, base, inv, bs, bsi);
        }
    } else {
        // Software pipeline: next iteration's loads issue before this body.
        int q = q0 + threadIdx.x;               // always < q1 (THREADS <= SEG_Q)
        float4 lc = ldg_stream256(lg + q);
        float4 uc = ldg_stream256(uu + q);
        for (int qn = q + THREADS; qn < q1; qn += THREADS) {
            float4 ln = ldg_stream256(lg + qn);
            float4 un = ldg_stream256(uu + qn);
            body4(lc, uc, q << 2, inv, bs, bsi);
            lc = ln; uc = un; q = qn;
        }
        body4(lc, uc, q << 2, inv, bs, bsi);
    }

    // Block reduction on packed keys
    unsigned long long kg = pack_key(bg, bgi);
    unsigned long long ks = pack_key(bs, bsi);

    #pragma unroll
    for (int o = 16; o > 0; o >>= 1) {
        kg = kmax64(kg, __shfl_xor_sync(0xffffffffu, kg, o));
        ks = kmax64(ks, __shfl_xor_sync(0xffffffffu, ks, o));
    }

    __shared__ unsigned long long sg[THREADS / 32];
    __shared__ unsigned long long ss[THREADS / 32];
    const int wid  = threadIdx.x >> 5;
    const int lane = threadIdx.x & 31;
    if (lane == 0) { sg[wid] = kg; ss[wid] = ks; }
    __syncthreads();

    if (threadIdx.x == 0) {
        #pragma unroll
        for (int i = 1; i < THREADS / 32; i++) {
            kg = kmax64(kg, sg[i]);
            ks = kmax64(ks, ss[i]);
        }
        d_part_g[row * SPLIT + seg] = kg;
        d_part_s[row * SPLIT + seg] = ks;

        __threadfence();                       // publish partials
        int old = atomicAdd(&d_count[row], 1);
        if (old == SPLIT - 1) {
            d_count[row] = 0;                  // self-reset for next replay
            __threadfence();
            unsigned long long mg = 0ull, ms = 0ull;
            #pragma unroll
            for (int i = 0; i < SPLIT; i++) {
                mg = kmax64(mg, d_part_g[row * SPLIT + i]);
                ms = kmax64(ms, d_part_s[row * SPLIT + i]);
            }
            int ig = (int)~(unsigned int)mg;
            int is = (int)~(unsigned int)ms;
            out[row] = (float)(need_greedy ? ig : is);
        }
    }
}

extern "C" void kernel_launch(void* const* d_in, const int* in_sizes, int n_in,
                              void* d_out, int out_size) {
    const float* logits = (const float*)d_in[0];
    const float* temps  = (const float*)d_in[1];
    const float* u      = (const float*)d_in[2];
    float* out = (float*)d_out;

    dim3 grid(SPLIT, B_ROWS);
    sampler_fused_kernel<<<grid, THREADS>>>(logits, temps, u, out);
}